// round 5
// baseline (speedup 1.0000x reference)
#include <cuda_runtime.h>

#define BB    8
#define NMAX  128
#define HH    192
#define WW    256
#define INV_DOWN 0.125f
#define NBOX  (BB * NMAX)   // 1024 warps, one block = one warp = one box

__device__ float        g_err_img[BB];
__device__ float        g_cnt_img[BB];
__device__ unsigned int g_count = 0;

// Antiderivative of the bilinear hat kernel, clipped to [-1, 1] (branchless)
__device__ __forceinline__ float hatP(float u) {
    u = fminf(1.0f, fmaxf(-1.0f, u));
    float neg = 0.5f * (u + 1.0f) * (u + 1.0f);
    float pos = 0.5f + u - 0.5f * u * u;
    return (u <= 0.0f) ? neg : pos;
}

__device__ __forceinline__ unsigned atom_add_release_gpu(unsigned* addr, unsigned v) {
    unsigned old;
    asm volatile("atom.add.release.gpu.global.u32 %0, [%1], %2;"
                 : "=r"(old) : "l"(addr), "r"(v) : "memory");
    return old;
}

__global__ __launch_bounds__(32)
void fused_kernel(const float* __restrict__ den,     // [B, 1, H, W]
                  const float* __restrict__ hboxes,  // [B, NMAX, 5]
                  const float* __restrict__ post,    // [B, NMAX, H, W]
                  float* __restrict__ out)
{
    const int bn   = blockIdx.x;
    const int b    = bn >> 7;          // bn / NMAX
    const int lane = threadIdx.x;

    const float* box = hboxes + (size_t)bn * 5;
    const float lab = __ldg(box + 4);

    if (lab > 0.0f) {
        const float x1 = __ldg(box + 0) * INV_DOWN;
        const float y1 = __ldg(box + 1) * INV_DOWN;
        const float x2 = __ldg(box + 2) * INV_DOWN;
        const float y2 = __ldg(box + 3) * INV_DOWN;

        // Hat support (pad 1 each side; padded entries evaluate to exactly 0).
        const int ix0 = max(0, (int)floorf(x1) - 1);
        const int ix1 = min(WW - 1, (int)ceilf(x2) + 1);
        const int iy0 = max(0, (int)floorf(y1) - 1);
        const int iy1 = min(HH - 1, (int)ceilf(y2) + 1);
        const int nx = ix1 - ix0 + 1;   // <= ~21 < 32
        const int ny = iy1 - iy0 + 1;   // <= ~21

        // Per-lane x weight in a register; out-of-range lanes contribute 0.
        const bool inx = (lane < nx);
        const float fx = (float)(ix0 + lane);
        const float wxl = inx ? (hatP(x2 - fx) - hatP(x1 - fx)) : 0.0f;

        const float* denP  = den  + (size_t)b  * (HH * WW) + iy0 * WW + ix0 + lane;
        const float* postP = post + (size_t)bn * (HH * WW) + iy0 * WW + ix0 + lane;

        float acc = 0.0f;
        #pragma unroll 4
        for (int r = 0; r < ny; r++) {
            // Every lane computes wy for this row itself — no shuffle, no sync.
            const float fy = (float)(iy0 + r);
            const float wyr = hatP(y2 - fy) - hatP(y1 - fy);
            float d = 0.0f, p = 0.0f;
            if (inx) {
                d = __ldg(denP  + r * WW);
                p = __ldg(postP + r * WW);
            }
            acc += wyr * (d * p);
        }
        acc *= wxl;

        // Warp reduction
        #pragma unroll
        for (int o = 16; o > 0; o >>= 1)
            acc += __shfl_down_sync(0xffffffffu, acc, o);

        if (lane == 0) {
            atomicAdd(&g_err_img[b], fabsf(acc - 1.0f));
            atomicAdd(&g_cnt_img[b], 1.0f);
        }
    }

    // Arrival counter with release semantics (no L1-flushing full fence).
    unsigned is_last = 0;
    if (lane == 0)
        is_last = (atom_add_release_gpu(&g_count, 1u) == (unsigned)(NBOX - 1));
    is_last = __shfl_sync(0xffffffffu, is_last, 0);

    if (is_last) {
        if (lane == 0) {
            asm volatile("fence.acquire.gpu;" ::: "memory");
            float tot = 0.0f;
            #pragma unroll
            for (int i = 0; i < BB; i++) {
                float e = __ldcg(&g_err_img[i]);
                float v = __ldcg(&g_cnt_img[i]);
                tot += (v > 0.0f) ? (e / fmaxf(v, 1.0f)) : 0.0f;
            }
            out[0] = tot;
            // Reset accumulators for the next graph replay.
            #pragma unroll
            for (int i = 0; i < BB; i++) {
                g_err_img[i] = 0.0f;
                g_cnt_img[i] = 0.0f;
            }
            g_count = 0;
        }
    }
}

extern "C" void kernel_launch(void* const* d_in, const int* in_sizes, int n_in,
                              void* d_out, int out_size)
{
    // metadata order: cls(0), reg(1), off(2), den(3), fboxes(4), hboxes(5),
    //                 ctr_masks(6), post_probs(7)
    const float* den    = (const float*)d_in[3];
    const float* hboxes = (const float*)d_in[5];
    const float* post   = (const float*)d_in[7];
    float* out = (float*)d_out;

    fused_kernel<<<NBOX, 32>>>(den, hboxes, post, out);
}

// round 6
// speedup vs baseline: 1.4981x; 1.4981x over previous
#include <cuda_runtime.h>

#define BB    8
#define NMAX  128
#define HH    192
#define WW    256
#define INV_DOWN 0.125f
#define NBOX  (BB * NMAX)   // 1024 blocks, one per box

// Antiderivative of the bilinear hat kernel, clipped to [-1, 1]
__device__ __forceinline__ float hatP(float u) {
    u = fminf(1.0f, fmaxf(-1.0f, u));
    float neg = 0.5f * (u + 1.0f) * (u + 1.0f);
    float pos = 0.5f + u - 0.5f * u * u;
    return (u <= 0.0f) ? neg : pos;
}

__global__ __launch_bounds__(128)
void count_kernel(const float* __restrict__ den,     // [B, 1, H, W]
                  const float* __restrict__ hboxes,  // [B, NMAX, 5]
                  const float* __restrict__ post,    // [B, NMAX, H, W]
                  float* __restrict__ out)           // zeroed by memset node
{
    const int bn = blockIdx.x;
    const int b  = bn >> 7;            // bn / NMAX
    const int t  = threadIdx.x;

    const float* box = hboxes + (size_t)bn * 5;
    const float lab = __ldg(box + 4);
    if (lab <= 0.0f) return;           // invalid box: contributes nothing

    // --- num_b: count of valid boxes in this image (redundant per block,
    //     L2-hot after first touch). 128 threads -> one label each.
    const float myLab = __ldg(hboxes + (size_t)b * NMAX * 5 + t * 5 + 4);
    const unsigned bal = __ballot_sync(0xffffffffu, myLab > 0.0f);
    __shared__ int s_cnt[4];
    if ((t & 31) == 0) s_cnt[t >> 5] = __popc(bal);

    // --- box geometry + separable hat weights
    const float x1 = __ldg(box + 0) * INV_DOWN;
    const float y1 = __ldg(box + 1) * INV_DOWN;
    const float x2 = __ldg(box + 2) * INV_DOWN;
    const float y2 = __ldg(box + 3) * INV_DOWN;

    const int ix0 = max(0, (int)floorf(x1) - 1);
    const int ix1 = min(WW - 1, (int)ceilf(x2) + 1);
    const int iy0 = max(0, (int)floorf(y1) - 1);
    const int iy1 = min(HH - 1, (int)ceilf(y2) + 1);
    const int nx = ix1 - ix0 + 1;      // <= ~21
    const int ny = iy1 - iy0 + 1;      // <= ~21

    __shared__ float wx[32];
    __shared__ float wy[32];
    if (t < nx) {
        float fx = (float)(ix0 + t);
        wx[t] = hatP(x2 - fx) - hatP(x1 - fx);
    }
    if (t < ny) {
        float fy = (float)(iy0 + t);
        wy[t] = hatP(y2 - fy) - hatP(y1 - fy);
    }
    __syncthreads();

    const int num = s_cnt[0] + s_cnt[1] + s_cnt[2] + s_cnt[3];  // >= 1 here

    // --- flat cell loop over the support region
    const float* denB  = den  + (size_t)b  * (HH * WW);
    const float* postN = post + (size_t)bn * (HH * WW);

    const int total = nx * ny;
    float acc = 0.0f;
    #pragma unroll 4
    for (int k = t; k < total; k += 128) {
        const int jy = k / nx;
        const int jx = k - jy * nx;
        const int idx = (iy0 + jy) * WW + (ix0 + jx);
        acc += wy[jy] * wx[jx] * (__ldg(denB + idx) * __ldg(postN + idx));
    }

    // --- block reduction (4 warps)
    #pragma unroll
    for (int o = 16; o > 0; o >>= 1)
        acc += __shfl_down_sync(0xffffffffu, acc, o);

    __shared__ float warpsum[4];
    if ((t & 31) == 0) warpsum[t >> 5] = acc;
    __syncthreads();

    if (t == 0) {
        const float count = warpsum[0] + warpsum[1] + warpsum[2] + warpsum[3];
        // per_img = sum_i |c_i - 1| / num  ->  distribute division per box.
        atomicAdd(out, fabsf(count - 1.0f) / (float)num);
    }
}

extern "C" void kernel_launch(void* const* d_in, const int* in_sizes, int n_in,
                              void* d_out, int out_size)
{
    // metadata order: cls(0), reg(1), off(2), den(3), fboxes(4), hboxes(5),
    //                 ctr_masks(6), post_probs(7)
    const float* den    = (const float*)d_in[3];
    const float* hboxes = (const float*)d_in[5];
    const float* post   = (const float*)d_in[7];
    float* out = (float*)d_out;

    cudaMemsetAsync(out, 0, sizeof(float));          // graph-capturable memset node
    count_kernel<<<NBOX, 128>>>(den, hboxes, post, out);
}

// round 7
// speedup vs baseline: 1.5504x; 1.0349x over previous
#include <cuda_runtime.h>

#define BB    8
#define NMAX  128
#define HH    192
#define WW    256
#define INV_DOWN 0.125f
#define NBOX  (BB * NMAX)   // 1024 blocks, one per box

// Antiderivative of the bilinear hat kernel, clipped to [-1, 1] (branchless)
__device__ __forceinline__ float hatP(float u) {
    u = fminf(1.0f, fmaxf(-1.0f, u));
    float neg = 0.5f * (u + 1.0f) * (u + 1.0f);
    float pos = 0.5f + u - 0.5f * u * u;
    return (u <= 0.0f) ? neg : pos;
}

__global__ __launch_bounds__(128)
void count_kernel(const float* __restrict__ den,     // [B, 1, H, W]
                  const float* __restrict__ hboxes,  // [B, NMAX, 5]
                  const float* __restrict__ post,    // [B, NMAX, H, W]
                  float* __restrict__ out)           // zeroed by memset node
{
    const int bn = blockIdx.x;
    const int b  = bn >> 7;            // bn / NMAX
    const int t  = threadIdx.x;
    const int w  = t >> 5;
    const int lane = t & 31;

    const float* box = hboxes + (size_t)bn * 5;
    const float lab = __ldg(box + 4);
    if (lab <= 0.0f) return;           // uniform per block: whole CTA exits

    __shared__ int   s_cnt[4];
    __shared__ float s_sum[4];

    // num_b: 128 threads -> one label each; per-warp popc, combined after
    // the single __syncthreads below.
    const float myLab = __ldg(hboxes + (size_t)b * NMAX * 5 + t * 5 + 4);
    const unsigned bal = __ballot_sync(0xffffffffu, myLab > 0.0f);
    if (lane == 0) s_cnt[w] = __popc(bal);

    // Box geometry (all in registers; weights computed inline per cell)
    const float x1 = __ldg(box + 0) * INV_DOWN;
    const float y1 = __ldg(box + 1) * INV_DOWN;
    const float x2 = __ldg(box + 2) * INV_DOWN;
    const float y2 = __ldg(box + 3) * INV_DOWN;

    const int ix0 = max(0, (int)floorf(x1) - 1);
    const int ix1 = min(WW - 1, (int)ceilf(x2) + 1);
    const int iy0 = max(0, (int)floorf(y1) - 1);
    const int iy1 = min(HH - 1, (int)ceilf(y2) + 1);
    const int nx = ix1 - ix0 + 1;      // <= ~24
    const int ny = iy1 - iy0 + 1;      // <= ~24
    const int total = nx * ny;         // <= ~576

    // Magic divide: jy = k / nx via umulhi, exact for k < 2^16.
    const unsigned magic = (unsigned)(((1ull << 32) + (unsigned)nx - 1) / (unsigned)nx);

    const float* denB  = den  + (size_t)b  * (HH * WW);
    const float* postN = post + (size_t)bn * (HH * WW);

    float acc = 0.0f;
    #pragma unroll 4
    for (int k = t; k < total; k += 128) {
        const int jy = (int)__umulhi((unsigned)k, magic);
        const int jx = k - jy * nx;
        const int x  = ix0 + jx;
        const int y  = iy0 + jy;
        const int idx = y * WW + x;
        const float d = __ldg(denB  + idx);
        const float p = __ldg(postN + idx);
        const float fx = (float)x;
        const float fy = (float)y;
        const float wxv = hatP(x2 - fx) - hatP(x1 - fx);
        const float wyv = hatP(y2 - fy) - hatP(y1 - fy);
        acc += (wxv * wyv) * (d * p);
    }

    // Warp reduce -> smem -> single sync -> thread 0 finalizes this box.
    #pragma unroll
    for (int o = 16; o > 0; o >>= 1)
        acc += __shfl_down_sync(0xffffffffu, acc, o);
    if (lane == 0) s_sum[w] = acc;
    __syncthreads();

    if (t == 0) {
        const float count = s_sum[0] + s_sum[1] + s_sum[2] + s_sum[3];
        const int   num   = s_cnt[0] + s_cnt[1] + s_cnt[2] + s_cnt[3]; // >= 1
        // per_img = sum_i |c_i - 1| / num_b, division distributed per box.
        atomicAdd(out, fabsf(count - 1.0f) * (1.0f / (float)num));
    }
}

extern "C" void kernel_launch(void* const* d_in, const int* in_sizes, int n_in,
                              void* d_out, int out_size)
{
    // metadata order: cls(0), reg(1), off(2), den(3), fboxes(4), hboxes(5),
    //                 ctr_masks(6), post_probs(7)
    const float* den    = (const float*)d_in[3];
    const float* hboxes = (const float*)d_in[5];
    const float* post   = (const float*)d_in[7];
    float* out = (float*)d_out;

    cudaMemsetAsync(out, 0, sizeof(float));          // graph memset node
    count_kernel<<<NBOX, 128>>>(den, hboxes, post, out);
}